// round 14
// baseline (speedup 1.0000x reference)
#include <cuda_runtime.h>
#include <cuda_fp16.h>
#include <cstdint>

// Problem constants
#define BNUM 4
#define SEQ  1024
#define EMBD 1024
#define NH   16
#define HD   64
#define BH   (BNUM * NH)
#define NEG_INF __int_as_float(0xff800000)

// Scratch (allocation-free contract: __device__ globals) — fp16 data plane
__device__ __half g_q[BH * SEQ * HD];          // [bh][s][d], pre-scaled by 1/32
__device__ __half g_k[BH * SEQ * HD];          // [bh][s][d]
__device__ __half g_vT[BH * HD * SEQ];         // [bh][d][s]
__device__ __half g_ctx[BNUM * SEQ * EMBD];    // concat ctx
__device__ __half g_xh[3 * BNUM * SEQ * EMBD]; // fp16-converted inputs k/v/q
// Transposed (B = [N,K] K-major) weights, fp16 (Wq pre-scaled by 1/32)
__device__ __half g_wT[3 * EMBD * EMBD];       // k/v/q
__device__ __half g_woT[EMBD * EMBD];

__device__ __forceinline__ uint32_t smem_u32(const void* p) {
    uint32_t a;
    asm("{ .reg .u64 t; cvta.to.shared.u64 t, %1; cvt.u32.u64 %0, t; }"
        : "=r"(a) : "l"(p));
    return a;
}

__device__ __forceinline__ void mma_f16(float (&d)[4], const uint32_t (&a)[4],
                                        const uint32_t b0, const uint32_t b1) {
    asm volatile(
        "mma.sync.aligned.m16n8k16.row.col.f32.f16.f16.f32 "
        "{%0,%1,%2,%3}, {%4,%5,%6,%7}, {%8,%9}, {%0,%1,%2,%3};"
        : "+f"(d[0]), "+f"(d[1]), "+f"(d[2]), "+f"(d[3])
        : "r"(a[0]), "r"(a[1]), "r"(a[2]), "r"(a[3]), "r"(b0), "r"(b1));
}

#define LDMX4(r, addr) \
    asm volatile("ldmatrix.sync.aligned.m8n8.x4.shared.b16 {%0,%1,%2,%3}, [%4];" \
        : "=r"((r)[0]), "=r"((r)[1]), "=r"((r)[2]), "=r"((r)[3]) : "r"(addr))

#define CP16(dst, src) \
    asm volatile("cp.async.cg.shared.global [%0], [%1], 16;" :: "r"(dst), "l"(src))
#define CP_COMMIT() asm volatile("cp.async.commit_group;" ::: "memory")
template<int N> __device__ __forceinline__ void cp_wait() {
    asm volatile("cp.async.wait_group %0;" :: "n"(N) : "memory");
}

// ---------------------------------------------------------------------------
// fp16 tensor-core GEMM v2: C[128x256] = A[M,K] @ Bt[N,K]^T, K=1024, BK=64.
// 8 warps (2m x 4n), warp tile 64x64 -> 128 B of smem fragments per MMA
// (was 192 at 32x64): the fp16 GEMM is smem-crossbar-bound, so the bigger
// warp tile attacks the binding resource. 1 CTA/SM (~200 regs), 3-stage
// cp.async, same 8x16B-chunk XOR swizzle.
// ---------------------------------------------------------------------------
#define A_BYTES 16384                   // 128 rows * 8 chunks * 16B
#define B_BYTES 32768                   // 256 rows * 8 chunks * 16B
#define STG_BYTES (A_BYTES + B_BYTES)
#define GEMM_SMEM (3 * STG_BYTES)       // 144KB

__device__ __forceinline__ void gemm_f16(const __half* __restrict__ A,
                                         const __half* __restrict__ Bt,
                                         char* sm, float (&c)[4][8][4])
{
    const int tid  = threadIdx.x;
    const int lane = tid & 31;
    const int warp = tid >> 5;
    const int m0   = blockIdx.x * 128;
    const int n0   = blockIdx.y * 256;
    const uint32_t sb = smem_u32(sm);

    auto issue = [&](int stage, int k0) {
        const uint32_t sa  = sb + stage * STG_BYTES;
        const uint32_t sbb = sa + A_BYTES;
        #pragma unroll
        for (int i = 0; i < 4; i++) {          // A: 1024 CP16
            const int idx = i * 256 + tid;
            const int row = idx >> 3, ch = idx & 7;
            const uint32_t off = (uint32_t)((row << 3) + (ch ^ (row & 7))) << 4;
            CP16(sa + off, A + (size_t)(m0 + row) * EMBD + k0 + ch * 8);
        }
        #pragma unroll
        for (int i = 0; i < 8; i++) {          // B: 2048 CP16
            const int idx = i * 256 + tid;
            const int row = idx >> 3, ch = idx & 7;
            const uint32_t off = (uint32_t)((row << 3) + (ch ^ (row & 7))) << 4;
            CP16(sbb + off, Bt + (size_t)(n0 + row) * EMBD + k0 + ch * 8);
        }
        CP_COMMIT();
    };

    issue(0, 0);
    issue(1, 64);

    const int l7   = lane & 7;
    const int wm   = (warp & 1) * 64;                  // 2m x 4n warp grid
    const int wn   = (warp >> 1) * 64;
    const int aRow = wm + l7 + ((lane >> 3) & 1) * 8;  // + mi*16
    const int aChO = lane >> 4;                        // klo/khi 16B chunk
    const int bRow = wn + l7 + (lane >> 4) * 8;        // + p*16
    const int bChO = (lane >> 3) & 1;

    for (int ch = 0; ch < 16; ch++) {
        const int st = ch % 3;
        if (ch < 14) cp_wait<1>(); else cp_wait<0>();
        __syncthreads();
        if (ch + 2 < 16) issue((ch + 2) % 3, (ch + 2) * 64);

        const uint32_t sa  = sb + st * STG_BYTES;
        const uint32_t sbb = sa + A_BYTES;

        #pragma unroll
        for (int ks = 0; ks < 4; ks++) {       // 4 k16 steps per BK=64
            uint32_t af[4][4], bq[4][4];
            #pragma unroll
            for (int mi = 0; mi < 4; mi++) {
                const int row = aRow + mi * 16;
                const uint32_t addr =
                    sa + ((uint32_t)((row << 3) + ((ks * 2 + aChO) ^ (row & 7))) << 4);
                LDMX4(af[mi], addr);
            }
            #pragma unroll
            for (int p = 0; p < 4; p++) {
                const int row = bRow + p * 16;
                const uint32_t addr =
                    sbb + ((uint32_t)((row << 3) + ((ks * 2 + bChO) ^ (row & 7))) << 4);
                LDMX4(bq[p], addr);
            }
            #pragma unroll
            for (int mi = 0; mi < 4; mi++)
                #pragma unroll
                for (int ni = 0; ni < 8; ni++)
                    mma_f16(c[mi][ni], af[mi],
                            bq[ni >> 1][(ni & 1) * 2],
                            bq[ni >> 1][(ni & 1) * 2 + 1]);
        }
    }
}

// Projection: A = g_xh[z], writes fp16 Q (pre-scaled via Wq) / K and V^T
__global__ __launch_bounds__(256, 1) void proj_tc()
{
    extern __shared__ char smc[];
    const int z = blockIdx.z;
    const __half* A  = g_xh + (size_t)z * BNUM * SEQ * EMBD;
    const __half* Bt = g_wT + (size_t)z * EMBD * EMBD;

    float c[4][8][4] = {};
    gemm_f16(A, Bt, smc, c);

    const int tid = threadIdx.x;
    const int lane = tid & 31, warp = tid >> 5;
    const int wm = (warp & 1) * 64, wn = (warp >> 1) * 64;
    const int g = lane >> 2, tg = lane & 3;
    const int m0 = blockIdx.x * 128, n0 = blockIdx.y * 256;

    if (z == 1) {
        // V -> g_vT [bh][d][s]
        #pragma unroll
        for (int mi = 0; mi < 4; mi++) {
            #pragma unroll
            for (int ni = 0; ni < 8; ni++) {
                const int n = n0 + wn + ni * 8 + tg * 2;
                const int h = n >> 6, d = n & 63;
                #pragma unroll
                for (int half = 0; half < 2; half++) {
                    const int m = m0 + wm + mi * 16 + g + half * 8;
                    const int b = m >> 10, s = m & 1023;
                    const size_t base = (size_t)(b * NH + h) * HD;
                    g_vT[(base + d)     * SEQ + s] = __float2half_rn(c[mi][ni][half * 2]);
                    g_vT[(base + d + 1) * SEQ + s] = __float2half_rn(c[mi][ni][half * 2 + 1]);
                }
            }
        }
    } else {
        __half* Out = (z == 0) ? g_k : g_q;
        #pragma unroll
        for (int mi = 0; mi < 4; mi++) {
            #pragma unroll
            for (int ni = 0; ni < 8; ni++) {
                const int n = n0 + wn + ni * 8 + tg * 2;
                const int h = n >> 6, d = n & 63;
                #pragma unroll
                for (int half = 0; half < 2; half++) {
                    const int m = m0 + wm + mi * 16 + g + half * 8;
                    const int b = m >> 10, s = m & 1023;
                    *(__half2*)&Out[((size_t)(b * NH + h) * SEQ + s) * HD + d] =
                        __floats2half2_rn(c[mi][ni][half * 2], c[mi][ni][half * 2 + 1]);
                }
            }
        }
    }
}

// Output projection: A = g_ctx (fp16), Bt = g_woT, bias + relu, fp32 out
__global__ __launch_bounds__(256, 1) void outproj_tc(const float* __restrict__ bo,
                                                     float* __restrict__ out)
{
    extern __shared__ char smc[];
    float c[4][8][4] = {};
    gemm_f16(g_ctx, g_woT, smc, c);

    const int tid = threadIdx.x;
    const int lane = tid & 31, warp = tid >> 5;
    const int wm = (warp & 1) * 64, wn = (warp >> 1) * 64;
    const int g = lane >> 2, tg = lane & 3;
    const int m0 = blockIdx.x * 128, n0 = blockIdx.y * 256;

    #pragma unroll
    for (int mi = 0; mi < 4; mi++) {
        #pragma unroll
        for (int ni = 0; ni < 8; ni++) {
            const int n = n0 + wn + ni * 8 + tg * 2;
            const float b0 = bo[n], b1 = bo[n + 1];
            #pragma unroll
            for (int half = 0; half < 2; half++) {
                const int m = m0 + wm + mi * 16 + g + half * 8;
                float2 v = make_float2(fmaxf(c[mi][ni][half * 2]     + b0, 0.0f),
                                       fmaxf(c[mi][ni][half * 2 + 1] + b1, 0.0f));
                *(float2*)&out[(size_t)m * EMBD + n] = v;
            }
        }
    }
}

// ---------------------------------------------------------------------------
// Input fp32 -> fp16 conversion (one pass)
// ---------------------------------------------------------------------------
__global__ __launch_bounds__(256) void cvt_inputs(const float* __restrict__ Xk,
                                                  const float* __restrict__ Xv,
                                                  const float* __restrict__ Xq)
{
    const int z = blockIdx.y;
    const float* X = (z == 0) ? Xk : (z == 1) ? Xv : Xq;
    __half* D = g_xh + (size_t)z * BNUM * SEQ * EMBD;
    const size_t i = (size_t)(blockIdx.x * 256 + threadIdx.x) * 8;
    float4 v1 = *(const float4*)(X + i);
    float4 v2 = *(const float4*)(X + i + 4);
    __half2 h[4] = { __floats2half2_rn(v1.x, v1.y), __floats2half2_rn(v1.z, v1.w),
                     __floats2half2_rn(v2.x, v2.y), __floats2half2_rn(v2.z, v2.w) };
    *(uint4*)(D + i) = *(uint4*)h;
}

// ---------------------------------------------------------------------------
// Merged weight transpose (one launch), fp32 -> fp16; Wq scaled by 1/32.
// ---------------------------------------------------------------------------
__global__ __launch_bounds__(256) void transpose_all(const float* __restrict__ Wk,
                                                     const float* __restrict__ Wv,
                                                     const float* __restrict__ Wq,
                                                     const float* __restrict__ Wo)
{
    __shared__ float sm[32][33];
    const int z = blockIdx.z;
    const int k0 = blockIdx.y * 32;
    const int tid = threadIdx.x;

    if (z < 3) {
        const float* W = (z == 0) ? Wk : (z == 1) ? Wv : Wq;
        const float scale = (z == 2) ? (1.0f / 32.0f) : 1.0f;
        __half* WT = g_wT + (size_t)z * EMBD * EMBD;
        const int h  = blockIdx.x & 15;
        const int d0 = (blockIdx.x >> 4) * 32;
        for (int idx = tid; idx < 1024; idx += 256) {
            const int r = idx >> 5, cdx = idx & 31;
            sm[r][cdx] = W[((size_t)h * EMBD + (k0 + r)) * HD + d0 + cdx] * scale;
        }
        __syncthreads();
        for (int idx = tid; idx < 1024; idx += 256) {
            const int dd = idx >> 5, kk = idx & 31;
            WT[(size_t)(h * HD + d0 + dd) * EMBD + k0 + kk] = __float2half_rn(sm[kk][dd]);
        }
    } else {
        const int n0 = blockIdx.x * 32;
        for (int idx = tid; idx < 1024; idx += 256) {
            const int r = idx >> 5, cdx = idx & 31;
            sm[r][cdx] = Wo[(size_t)(k0 + r) * EMBD + n0 + cdx];
        }
        __syncthreads();
        for (int idx = tid; idx < 1024; idx += 256) {
            const int rr = idx >> 5, cc = idx & 31;
            g_woT[(size_t)(n0 + rr) * EMBD + k0 + cc] = __float2half_rn(sm[cc][rr]);
        }
    }
}

// ---------------------------------------------------------------------------
// fp16 tensor-core flash attention, 128-thread CTAs (64 q rows), 3 CTAs/SM.
// ---------------------------------------------------------------------------
#define KP 72                                  // P pitch in halves (144B rows)
#define ATT_TILE 8192                          // 64 rows * 8 chunks * 16B
#define ATTN_SMEM (4 * ATT_TILE + 4 * 16 * KP * (int)sizeof(__half))

__device__ __forceinline__ uint32_t att_off(int row, int ch) {
    return (uint32_t)((row << 3) + (ch ^ (row & 7))) << 4;
}

__global__ __launch_bounds__(128, 3) void attn_tc()
{
    extern __shared__ char smc[];
    const uint32_t sb = smem_u32(smc);
    __half* Ps = (__half*)(smc + 4 * ATT_TILE);   // [4 warps][16 q][KP keys]

    const int bh = blockIdx.x;
    const int qt = 15 - blockIdx.y;       // heavy tiles first
    const int q0 = qt * 64;
    const int tid = threadIdx.x, lane = tid & 31, warp = tid >> 5;
    const int g = lane >> 2, tg = lane & 3;
    const int l7 = lane & 7;
    const int fRowO = l7 + (lane >> 4) * 8;      // B-fragment row offset
    const int fChO  = (lane >> 3) & 1;           // B-fragment chunk offset
    const int wq = q0 + warp * 16;

    const __half* Qg = g_q  + (size_t)bh * SEQ * HD;
    const __half* Kg = g_k  + (size_t)bh * SEQ * HD;
    const __half* Vg = g_vT + (size_t)bh * HD * SEQ;
    __half* Pw = Ps + warp * 16 * KP;

    // P A-fragment ldmatrix base (m16n8k16 a-frag lane mapping)
    const uint32_t pBase = smem_u32(Pw) +
        (uint32_t)(l7 + ((lane >> 3) & 1) * 8) * KP * 2 + (uint32_t)(lane >> 4) * 16;

    auto issueKV = [&](int kt) {
        const int k0 = kt * 64;
        const uint32_t kb = sb + (kt & 1) * ATT_TILE;
        const uint32_t vb = sb + 2 * ATT_TILE + (kt & 1) * ATT_TILE;
        #pragma unroll
        for (int i = 0; i < 4; i++) {
            const int idx = i * 128 + tid;
            const int row = idx >> 3, ch = idx & 7;
            const uint32_t o = att_off(row, ch);
            CP16(kb + o, Kg + (size_t)(k0 + row) * HD + ch * 8);
            CP16(vb + o, Vg + (size_t)row * SEQ + k0 + ch * 8);
        }
        CP_COMMIT();
    };

    // Q fragments (pre-scaled in gmem): 4 k16-steps over HD=64
    uint32_t aq[4][4];
    #pragma unroll
    for (int kk = 0; kk < 4; kk++) {
        aq[kk][0] = *(const uint32_t*)(Qg + (size_t)(wq + g)     * HD + kk * 16 + tg * 2);
        aq[kk][1] = *(const uint32_t*)(Qg + (size_t)(wq + g + 8) * HD + kk * 16 + tg * 2);
        aq[kk][2] = *(const uint32_t*)(Qg + (size_t)(wq + g)     * HD + kk * 16 + 8 + tg * 2);
        aq[kk][3] = *(const uint32_t*)(Qg + (size_t)(wq + g + 8) * HD + kk * 16 + 8 + tg * 2);
    }

    float o[8][4] = {};
    float m_r[2] = { NEG_INF, NEG_INF };
    float l_r[2] = { 0.0f, 0.0f };

    const int ktend = qt + 1;
    issueKV(0);

    for (int kt = 0; kt < ktend; kt++) {
        const int k0 = kt * 64;
        cp_wait<0>();
        __syncthreads();
        if (kt + 1 < ktend) issueKV(kt + 1);

        const uint32_t kb = sb + (kt & 1) * ATT_TILE;
        const uint32_t vb = sb + 2 * ATT_TILE + (kt & 1) * ATT_TILE;

        // S = (Q/32) K^T
        float cs[8][4] = {};
        #pragma unroll
        for (int kk = 0; kk < 4; kk++) {
            const int ch = 2 * kk + fChO;
            #pragma unroll
            for (int n16 = 0; n16 < 4; n16++) {
                uint32_t bk[4];
                LDMX4(bk, kb + att_off(n16 * 16 + fRowO, ch));
                mma_f16(cs[2 * n16],     aq[kk], bk[0], bk[1]);
                mma_f16(cs[2 * n16 + 1], aq[kk], bk[2], bk[3]);
            }
        }

        // causal mask (only the diagonal tile can cross)
        if (kt == qt) {
            #pragma unroll
            for (int ni = 0; ni < 8; ni++) {
                #pragma unroll
                for (int e = 0; e < 4; e++) {
                    const int q = wq + g + ((e >> 1) << 3);
                    const int k = k0 + ni * 8 + tg * 2 + (e & 1);
                    if (k > q) cs[ni][e] = NEG_INF;
                }
            }
        }

        // online softmax (rows g and g+8), quad reductions
        #pragma unroll
        for (int hh = 0; hh < 2; hh++) {
            float mx = NEG_INF;
            #pragma unroll
            for (int ni = 0; ni < 8; ni++)
                mx = fmaxf(mx, fmaxf(cs[ni][2 * hh], cs[ni][2 * hh + 1]));
            mx = fmaxf(mx, __shfl_xor_sync(0xffffffff, mx, 1));
            mx = fmaxf(mx, __shfl_xor_sync(0xffffffff, mx, 2));
            const float mnew = fmaxf(m_r[hh], mx);
            const float alpha = __expf(m_r[hh] - mnew);
            float sum = 0.0f;
            #pragma unroll
            for (int ni = 0; ni < 8; ni++) {
                const float p0 = __expf(cs[ni][2 * hh]     - mnew);
                const float p1 = __expf(cs[ni][2 * hh + 1] - mnew);
                cs[ni][2 * hh] = p0; cs[ni][2 * hh + 1] = p1;
                sum += p0 + p1;
            }
            sum += __shfl_xor_sync(0xffffffff, sum, 1);
            sum += __shfl_xor_sync(0xffffffff, sum, 2);
            l_r[hh] = l_r[hh] * alpha + sum;
            m_r[hh] = mnew;
            #pragma unroll
            for (int ni = 0; ni < 8; ni++) {
                o[ni][2 * hh] *= alpha; o[ni][2 * hh + 1] *= alpha;
            }
        }

        // P -> warp-private SMEM (fp16)
        #pragma unroll
        for (int ni = 0; ni < 8; ni++) {
            *(__half2*)&Pw[g * KP + ni * 8 + tg * 2] =
                __floats2half2_rn(cs[ni][0], cs[ni][1]);
            *(__half2*)&Pw[(g + 8) * KP + ni * 8 + tg * 2] =
                __floats2half2_rn(cs[ni][2], cs[ni][3]);
        }
        __syncwarp();

        // O += P V   (P A-frags and V^T B-frags via ldmatrix, 4 k16-steps)
        #pragma unroll
        for (int kk = 0; kk < 4; kk++) {
            uint32_t ap[4];
            LDMX4(ap, pBase + kk * 32);
            const int ch = 2 * kk + fChO;
            #pragma unroll
            for (int n16 = 0; n16 < 4; n16++) {
                uint32_t bv[4];
                LDMX4(bv, vb + att_off(n16 * 16 + fRowO, ch));
                mma_f16(o[2 * n16],     ap, bv[0], bv[1]);
                mma_f16(o[2 * n16 + 1], ap, bv[2], bv[3]);
            }
        }
    }

    // epilogue: normalize and write concat ctx (fp16 for outproj)
    const int b = bh >> 4;
    const int h4 = bh & 15;
    const float inv0 = 1.0f / l_r[0];
    const float inv1 = 1.0f / l_r[1];
    #pragma unroll
    for (int ni = 0; ni < 8; ni++) {
        const int d = h4 * 64 + ni * 8 + tg * 2;
        const int r0 = wq + g, r1 = wq + g + 8;
        *(__half2*)&g_ctx[(size_t)(b * SEQ + r0) * EMBD + d] =
            __floats2half2_rn(o[ni][0] * inv0, o[ni][1] * inv0);
        *(__half2*)&g_ctx[(size_t)(b * SEQ + r1) * EMBD + d] =
            __floats2half2_rn(o[ni][2] * inv1, o[ni][3] * inv1);
    }
}

// ---------------------------------------------------------------------------
extern "C" void kernel_launch(void* const* d_in, const int* in_sizes, int n_in,
                              void* d_out, int out_size)
{
    const float* Xk = (const float*)d_in[0];
    const float* Xv = (const float*)d_in[1];
    const float* Xq = (const float*)d_in[2];
    const float* Wk = (const float*)d_in[3];
    const float* Wv = (const float*)d_in[4];
    const float* Wq = (const float*)d_in[5];
    const float* Wo = (const float*)d_in[6];
    const float* bo = (const float*)d_in[7];
    float* out = (float*)d_out;

    cudaFuncSetAttribute(proj_tc, cudaFuncAttributeMaxDynamicSharedMemorySize, GEMM_SMEM);
    cudaFuncSetAttribute(outproj_tc, cudaFuncAttributeMaxDynamicSharedMemorySize, GEMM_SMEM);
    cudaFuncSetAttribute(attn_tc, cudaFuncAttributeMaxDynamicSharedMemorySize, ATTN_SMEM);

    // 0) convert inputs to fp16 + transpose weights (Wq pre-scaled by 1/32)
    cvt_inputs<<<dim3(2048, 3), 256>>>(Xk, Xv, Xq);
    transpose_all<<<dim3(32, 32, 4), 256>>>(Wk, Wv, Wq, Wo);
    // 1) QKV projections (fp16 mma, 128x256 CTA / 64x64 warp tile)
    proj_tc<<<dim3(32, 4, 3), 256, GEMM_SMEM>>>();
    // 2) causal flash attention (fp16 mma, 64-q blocks, 3 CTAs/SM)
    attn_tc<<<dim3(BH, 16), 128, ATTN_SMEM>>>();
    // 3) output projection + bias + relu (fp16 mma)
    outproj_tc<<<dim3(32, 4), 256, GEMM_SMEM>>>(bo, out);
}

// round 15
// speedup vs baseline: 1.0524x; 1.0524x over previous
#include <cuda_runtime.h>
#include <cuda_fp16.h>
#include <cstdint>

// Problem constants
#define BNUM 4
#define SEQ  1024
#define EMBD 1024
#define NH   16
#define HD   64
#define BH   (BNUM * NH)
#define NEG_INF __int_as_float(0xff800000)

// Scratch (allocation-free contract: __device__ globals) — fp16 data plane
__device__ __half g_q[BH * SEQ * HD];          // [bh][s][d], pre-scaled by 1/32
__device__ __half g_k[BH * SEQ * HD];          // [bh][s][d]
__device__ __half g_vT[BH * HD * SEQ];         // [bh][d][s]
__device__ __half g_ctx[BNUM * SEQ * EMBD];    // concat ctx
__device__ __half g_xh[3 * BNUM * SEQ * EMBD]; // fp16-converted inputs k/v/q
// Transposed (B = [N,K] K-major) weights, fp16 (Wq pre-scaled by 1/32)
__device__ __half g_wT[3 * EMBD * EMBD];       // k/v/q
__device__ __half g_woT[EMBD * EMBD];

__device__ __forceinline__ uint32_t smem_u32(const void* p) {
    uint32_t a;
    asm("{ .reg .u64 t; cvta.to.shared.u64 t, %1; cvt.u32.u64 %0, t; }"
        : "=r"(a) : "l"(p));
    return a;
}

__device__ __forceinline__ void mma_f16(float (&d)[4], const uint32_t (&a)[4],
                                        const uint32_t b0, const uint32_t b1) {
    asm volatile(
        "mma.sync.aligned.m16n8k16.row.col.f32.f16.f16.f32 "
        "{%0,%1,%2,%3}, {%4,%5,%6,%7}, {%8,%9}, {%0,%1,%2,%3};"
        : "+f"(d[0]), "+f"(d[1]), "+f"(d[2]), "+f"(d[3])
        : "r"(a[0]), "r"(a[1]), "r"(a[2]), "r"(a[3]), "r"(b0), "r"(b1));
}

#define LDMX4(r, addr) \
    asm volatile("ldmatrix.sync.aligned.m8n8.x4.shared.b16 {%0,%1,%2,%3}, [%4];" \
        : "=r"((r)[0]), "=r"((r)[1]), "=r"((r)[2]), "=r"((r)[3]) : "r"(addr))

#define CP16(dst, src) \
    asm volatile("cp.async.cg.shared.global [%0], [%1], 16;" :: "r"(dst), "l"(src))
#define CP_COMMIT() asm volatile("cp.async.commit_group;" ::: "memory")
template<int N> __device__ __forceinline__ void cp_wait() {
    asm volatile("cp.async.wait_group %0;" :: "n"(N) : "memory");
}

// ---------------------------------------------------------------------------
// fp16 tensor-core GEMM (R13 config — best measured): C[128x128] = A @ Bt^T,
// K=1024, BK=64, 8 warps (4m x 2n), warp tile 32x64, 3-stage cp.async,
// ldmatrix fragments, 2 CTAs/SM. 8x16B-chunk XOR swizzle (64 fp16 = 128B/row).
// ---------------------------------------------------------------------------
#define TILE_BYTES 16384                // 128 rows * 8 chunks * 16B
#define GEMM_SMEM  (3 * 2 * TILE_BYTES) // 96KB

__device__ __forceinline__ void gemm_f16(const __half* __restrict__ A,
                                         const __half* __restrict__ Bt,
                                         char* sm, float (&c)[2][8][4])
{
    const int tid  = threadIdx.x;
    const int lane = tid & 31;
    const int warp = tid >> 5;
    const int m0   = blockIdx.x * 128;
    const int n0   = blockIdx.y * 128;
    const uint32_t sb = smem_u32(sm);

    auto issue = [&](int stage, int k0) {
        const uint32_t sa  = sb + stage * 2 * TILE_BYTES;
        const uint32_t sbb = sa + TILE_BYTES;
        #pragma unroll
        for (int i = 0; i < 4; i++) {
            const int idx = i * 256 + tid;
            const int row = idx >> 3, ch = idx & 7;
            const uint32_t off = (uint32_t)((row << 3) + (ch ^ (row & 7))) << 4;
            CP16(sa  + off, A  + (size_t)(m0 + row) * EMBD + k0 + ch * 8);
            CP16(sbb + off, Bt + (size_t)(n0 + row) * EMBD + k0 + ch * 8);
        }
        CP_COMMIT();
    };

    issue(0, 0);
    issue(1, 64);

    const int l7   = lane & 7;
    const int wm   = (warp & 3) * 32;                  // 4x2 warp grid
    const int wn   = (warp >> 2) * 64;
    const int aRow = wm + l7 + ((lane >> 3) & 1) * 8;  // + mi*16
    const int aChO = lane >> 4;                        // klo/khi 16B chunk
    const int bRow = wn + l7 + (lane >> 4) * 8;        // + p*16
    const int bChO = (lane >> 3) & 1;

    for (int ch = 0; ch < 16; ch++) {
        const int st = ch % 3;
        if (ch < 14) cp_wait<1>(); else cp_wait<0>();
        __syncthreads();
        if (ch + 2 < 16) issue((ch + 2) % 3, (ch + 2) * 64);

        const uint32_t sa  = sb + st * 2 * TILE_BYTES;
        const uint32_t sbb = sa + TILE_BYTES;

        #pragma unroll
        for (int ks = 0; ks < 4; ks++) {       // 4 k16 steps per BK=64
            uint32_t af[2][4], bq[4][4];
            #pragma unroll
            for (int mi = 0; mi < 2; mi++) {
                const int row = aRow + mi * 16;
                const uint32_t addr =
                    sa + ((uint32_t)((row << 3) + ((ks * 2 + aChO) ^ (row & 7))) << 4);
                LDMX4(af[mi], addr);
            }
            #pragma unroll
            for (int p = 0; p < 4; p++) {
                const int row = bRow + p * 16;
                const uint32_t addr =
                    sbb + ((uint32_t)((row << 3) + ((ks * 2 + bChO) ^ (row & 7))) << 4);
                LDMX4(bq[p], addr);
            }
            #pragma unroll
            for (int mi = 0; mi < 2; mi++)
                #pragma unroll
                for (int ni = 0; ni < 8; ni++)
                    mma_f16(c[mi][ni], af[mi],
                            bq[ni >> 1][(ni & 1) * 2],
                            bq[ni >> 1][(ni & 1) * 2 + 1]);
        }
    }
}

// Projection: A = g_xh[z], writes fp16 Q (pre-scaled via Wq) / K and V^T
__global__ __launch_bounds__(256, 2) void proj_tc()
{
    extern __shared__ char smc[];
    const int z = blockIdx.z;
    const __half* A  = g_xh + (size_t)z * BNUM * SEQ * EMBD;
    const __half* Bt = g_wT + (size_t)z * EMBD * EMBD;

    float c[2][8][4] = {};
    gemm_f16(A, Bt, smc, c);

    const int tid = threadIdx.x;
    const int lane = tid & 31, warp = tid >> 5;
    const int wm = (warp & 3) * 32, wn = (warp >> 2) * 64;
    const int g = lane >> 2, tg = lane & 3;
    const int m0 = blockIdx.x * 128, n0 = blockIdx.y * 128;

    if (z == 1) {
        // V -> g_vT [bh][d][s]
        #pragma unroll
        for (int mi = 0; mi < 2; mi++) {
            #pragma unroll
            for (int ni = 0; ni < 8; ni++) {
                const int n = n0 + wn + ni * 8 + tg * 2;
                const int h = n >> 6, d = n & 63;
                #pragma unroll
                for (int half = 0; half < 2; half++) {
                    const int m = m0 + wm + mi * 16 + g + half * 8;
                    const int b = m >> 10, s = m & 1023;
                    const size_t base = (size_t)(b * NH + h) * HD;
                    g_vT[(base + d)     * SEQ + s] = __float2half_rn(c[mi][ni][half * 2]);
                    g_vT[(base + d + 1) * SEQ + s] = __float2half_rn(c[mi][ni][half * 2 + 1]);
                }
            }
        }
    } else {
        __half* Out = (z == 0) ? g_k : g_q;
        #pragma unroll
        for (int mi = 0; mi < 2; mi++) {
            #pragma unroll
            for (int ni = 0; ni < 8; ni++) {
                const int n = n0 + wn + ni * 8 + tg * 2;
                const int h = n >> 6, d = n & 63;
                #pragma unroll
                for (int half = 0; half < 2; half++) {
                    const int m = m0 + wm + mi * 16 + g + half * 8;
                    const int b = m >> 10, s = m & 1023;
                    *(__half2*)&Out[((size_t)(b * NH + h) * SEQ + s) * HD + d] =
                        __floats2half2_rn(c[mi][ni][half * 2], c[mi][ni][half * 2 + 1]);
                }
            }
        }
    }
}

// Output projection: A = g_ctx (fp16), Bt = g_woT, bias + relu, fp32 out
__global__ __launch_bounds__(256, 2) void outproj_tc(const float* __restrict__ bo,
                                                     float* __restrict__ out)
{
    extern __shared__ char smc[];
    float c[2][8][4] = {};
    gemm_f16(g_ctx, g_woT, smc, c);

    const int tid = threadIdx.x;
    const int lane = tid & 31, warp = tid >> 5;
    const int wm = (warp & 3) * 32, wn = (warp >> 2) * 64;
    const int g = lane >> 2, tg = lane & 3;
    const int m0 = blockIdx.x * 128, n0 = blockIdx.y * 128;

    #pragma unroll
    for (int mi = 0; mi < 2; mi++) {
        #pragma unroll
        for (int ni = 0; ni < 8; ni++) {
            const int n = n0 + wn + ni * 8 + tg * 2;
            const float b0 = bo[n], b1 = bo[n + 1];
            #pragma unroll
            for (int half = 0; half < 2; half++) {
                const int m = m0 + wm + mi * 16 + g + half * 8;
                float2 v = make_float2(fmaxf(c[mi][ni][half * 2]     + b0, 0.0f),
                                       fmaxf(c[mi][ni][half * 2 + 1] + b1, 0.0f));
                *(float2*)&out[(size_t)m * EMBD + n] = v;
            }
        }
    }
}

// ---------------------------------------------------------------------------
// Input fp32 -> fp16 conversion (one pass)
// ---------------------------------------------------------------------------
__global__ __launch_bounds__(256) void cvt_inputs(const float* __restrict__ Xk,
                                                  const float* __restrict__ Xv,
                                                  const float* __restrict__ Xq)
{
    const int z = blockIdx.y;
    const float* X = (z == 0) ? Xk : (z == 1) ? Xv : Xq;
    __half* D = g_xh + (size_t)z * BNUM * SEQ * EMBD;
    const size_t i = (size_t)(blockIdx.x * 256 + threadIdx.x) * 8;
    float4 v1 = *(const float4*)(X + i);
    float4 v2 = *(const float4*)(X + i + 4);
    __half2 h[4] = { __floats2half2_rn(v1.x, v1.y), __floats2half2_rn(v1.z, v1.w),
                     __floats2half2_rn(v2.x, v2.y), __floats2half2_rn(v2.z, v2.w) };
    *(uint4*)(D + i) = *(uint4*)h;
}

// ---------------------------------------------------------------------------
// Merged weight transpose (one launch), fp32 -> fp16; Wq scaled by 1/32.
// ---------------------------------------------------------------------------
__global__ __launch_bounds__(256) void transpose_all(const float* __restrict__ Wk,
                                                     const float* __restrict__ Wv,
                                                     const float* __restrict__ Wq,
                                                     const float* __restrict__ Wo)
{
    __shared__ float sm[32][33];
    const int z = blockIdx.z;
    const int k0 = blockIdx.y * 32;
    const int tid = threadIdx.x;

    if (z < 3) {
        const float* W = (z == 0) ? Wk : (z == 1) ? Wv : Wq;
        const float scale = (z == 2) ? (1.0f / 32.0f) : 1.0f;
        __half* WT = g_wT + (size_t)z * EMBD * EMBD;
        const int h  = blockIdx.x & 15;
        const int d0 = (blockIdx.x >> 4) * 32;
        for (int idx = tid; idx < 1024; idx += 256) {
            const int r = idx >> 5, cdx = idx & 31;
            sm[r][cdx] = W[((size_t)h * EMBD + (k0 + r)) * HD + d0 + cdx] * scale;
        }
        __syncthreads();
        for (int idx = tid; idx < 1024; idx += 256) {
            const int dd = idx >> 5, kk = idx & 31;
            WT[(size_t)(h * HD + d0 + dd) * EMBD + k0 + kk] = __float2half_rn(sm[kk][dd]);
        }
    } else {
        const int n0 = blockIdx.x * 32;
        for (int idx = tid; idx < 1024; idx += 256) {
            const int r = idx >> 5, cdx = idx & 31;
            sm[r][cdx] = Wo[(size_t)(k0 + r) * EMBD + n0 + cdx];
        }
        __syncthreads();
        for (int idx = tid; idx < 1024; idx += 256) {
            const int rr = idx >> 5, cc = idx & 31;
            g_woT[(size_t)(n0 + rr) * EMBD + k0 + cc] = __float2half_rn(sm[cc][rr]);
        }
    }
}

// ---------------------------------------------------------------------------
// fp16 tensor-core flash attention, 128-thread CTAs (64 q rows), 3 CTAs/SM
// (R14 config — best measured for attn).
// ---------------------------------------------------------------------------
#define KP 72                                  // P pitch in halves (144B rows)
#define ATT_TILE 8192                          // 64 rows * 8 chunks * 16B
#define ATTN_SMEM (4 * ATT_TILE + 4 * 16 * KP * (int)sizeof(__half))

__device__ __forceinline__ uint32_t att_off(int row, int ch) {
    return (uint32_t)((row << 3) + (ch ^ (row & 7))) << 4;
}

__global__ __launch_bounds__(128, 3) void attn_tc()
{
    extern __shared__ char smc[];
    const uint32_t sb = smem_u32(smc);
    __half* Ps = (__half*)(smc + 4 * ATT_TILE);   // [4 warps][16 q][KP keys]

    const int bh = blockIdx.x;
    const int qt = 15 - blockIdx.y;       // heavy tiles first
    const int q0 = qt * 64;
    const int tid = threadIdx.x, lane = tid & 31, warp = tid >> 5;
    const int g = lane >> 2, tg = lane & 3;
    const int l7 = lane & 7;
    const int fRowO = l7 + (lane >> 4) * 8;      // B-fragment row offset
    const int fChO  = (lane >> 3) & 1;           // B-fragment chunk offset
    const int wq = q0 + warp * 16;

    const __half* Qg = g_q  + (size_t)bh * SEQ * HD;
    const __half* Kg = g_k  + (size_t)bh * SEQ * HD;
    const __half* Vg = g_vT + (size_t)bh * HD * SEQ;
    __half* Pw = Ps + warp * 16 * KP;

    // P A-fragment ldmatrix base (m16n8k16 a-frag lane mapping)
    const uint32_t pBase = smem_u32(Pw) +
        (uint32_t)(l7 + ((lane >> 3) & 1) * 8) * KP * 2 + (uint32_t)(lane >> 4) * 16;

    auto issueKV = [&](int kt) {
        const int k0 = kt * 64;
        const uint32_t kb = sb + (kt & 1) * ATT_TILE;
        const uint32_t vb = sb + 2 * ATT_TILE + (kt & 1) * ATT_TILE;
        #pragma unroll
        for (int i = 0; i < 4; i++) {
            const int idx = i * 128 + tid;
            const int row = idx >> 3, ch = idx & 7;
            const uint32_t o = att_off(row, ch);
            CP16(kb + o, Kg + (size_t)(k0 + row) * HD + ch * 8);
            CP16(vb + o, Vg + (size_t)row * SEQ + k0 + ch * 8);
        }
        CP_COMMIT();
    };

    // Q fragments (pre-scaled in gmem): 4 k16-steps over HD=64
    uint32_t aq[4][4];
    #pragma unroll
    for (int kk = 0; kk < 4; kk++) {
        aq[kk][0] = *(const uint32_t*)(Qg + (size_t)(wq + g)     * HD + kk * 16 + tg * 2);
        aq[kk][1] = *(const uint32_t*)(Qg + (size_t)(wq + g + 8) * HD + kk * 16 + tg * 2);
        aq[kk][2] = *(const uint32_t*)(Qg + (size_t)(wq + g)     * HD + kk * 16 + 8 + tg * 2);
        aq[kk][3] = *(const uint32_t*)(Qg + (size_t)(wq + g + 8) * HD + kk * 16 + 8 + tg * 2);
    }

    float o[8][4] = {};
    float m_r[2] = { NEG_INF, NEG_INF };
    float l_r[2] = { 0.0f, 0.0f };

    const int ktend = qt + 1;
    issueKV(0);

    for (int kt = 0; kt < ktend; kt++) {
        const int k0 = kt * 64;
        cp_wait<0>();
        __syncthreads();
        if (kt + 1 < ktend) issueKV(kt + 1);

        const uint32_t kb = sb + (kt & 1) * ATT_TILE;
        const uint32_t vb = sb + 2 * ATT_TILE + (kt & 1) * ATT_TILE;

        // S = (Q/32) K^T
        float cs[8][4] = {};
        #pragma unroll
        for (int kk = 0; kk < 4; kk++) {
            const int ch = 2 * kk + fChO;
            #pragma unroll
            for (int n16 = 0; n16 < 4; n16++) {
                uint32_t bk[4];
                LDMX4(bk, kb + att_off(n16 * 16 + fRowO, ch));
                mma_f16(cs[2 * n16],     aq[kk], bk[0], bk[1]);
                mma_f16(cs[2 * n16 + 1], aq[kk], bk[2], bk[3]);
            }
        }

        // causal mask (only the diagonal tile can cross)
        if (kt == qt) {
            #pragma unroll
            for (int ni = 0; ni < 8; ni++) {
                #pragma unroll
                for (int e = 0; e < 4; e++) {
                    const int q = wq + g + ((e >> 1) << 3);
                    const int k = k0 + ni * 8 + tg * 2 + (e & 1);
                    if (k > q) cs[ni][e] = NEG_INF;
                }
            }
        }

        // online softmax (rows g and g+8), quad reductions
        #pragma unroll
        for (int hh = 0; hh < 2; hh++) {
            float mx = NEG_INF;
            #pragma unroll
            for (int ni = 0; ni < 8; ni++)
                mx = fmaxf(mx, fmaxf(cs[ni][2 * hh], cs[ni][2 * hh + 1]));
            mx = fmaxf(mx, __shfl_xor_sync(0xffffffff, mx, 1));
            mx = fmaxf(mx, __shfl_xor_sync(0xffffffff, mx, 2));
            const float mnew = fmaxf(m_r[hh], mx);
            const float alpha = __expf(m_r[hh] - mnew);
            float sum = 0.0f;
            #pragma unroll
            for (int ni = 0; ni < 8; ni++) {
                const float p0 = __expf(cs[ni][2 * hh]     - mnew);
                const float p1 = __expf(cs[ni][2 * hh + 1] - mnew);
                cs[ni][2 * hh] = p0; cs[ni][2 * hh + 1] = p1;
                sum += p0 + p1;
            }
            sum += __shfl_xor_sync(0xffffffff, sum, 1);
            sum += __shfl_xor_sync(0xffffffff, sum, 2);
            l_r[hh] = l_r[hh] * alpha + sum;
            m_r[hh] = mnew;
            #pragma unroll
            for (int ni = 0; ni < 8; ni++) {
                o[ni][2 * hh] *= alpha; o[ni][2 * hh + 1] *= alpha;
            }
        }

        // P -> warp-private SMEM (fp16)
        #pragma unroll
        for (int ni = 0; ni < 8; ni++) {
            *(__half2*)&Pw[g * KP + ni * 8 + tg * 2] =
                __floats2half2_rn(cs[ni][0], cs[ni][1]);
            *(__half2*)&Pw[(g + 8) * KP + ni * 8 + tg * 2] =
                __floats2half2_rn(cs[ni][2], cs[ni][3]);
        }
        __syncwarp();

        // O += P V   (P A-frags and V^T B-frags via ldmatrix, 4 k16-steps)
        #pragma unroll
        for (int kk = 0; kk < 4; kk++) {
            uint32_t ap[4];
            LDMX4(ap, pBase + kk * 32);
            const int ch = 2 * kk + fChO;
            #pragma unroll
            for (int n16 = 0; n16 < 4; n16++) {
                uint32_t bv[4];
                LDMX4(bv, vb + att_off(n16 * 16 + fRowO, ch));
                mma_f16(o[2 * n16],     ap, bv[0], bv[1]);
                mma_f16(o[2 * n16 + 1], ap, bv[2], bv[3]);
            }
        }
    }

    // epilogue: normalize and write concat ctx (fp16 for outproj)
    const int b = bh >> 4;
    const int h4 = bh & 15;
    const float inv0 = 1.0f / l_r[0];
    const float inv1 = 1.0f / l_r[1];
    #pragma unroll
    for (int ni = 0; ni < 8; ni++) {
        const int d = h4 * 64 + ni * 8 + tg * 2;
        const int r0 = wq + g, r1 = wq + g + 8;
        *(__half2*)&g_ctx[(size_t)(b * SEQ + r0) * EMBD + d] =
            __floats2half2_rn(o[ni][0] * inv0, o[ni][1] * inv0);
        *(__half2*)&g_ctx[(size_t)(b * SEQ + r1) * EMBD + d] =
            __floats2half2_rn(o[ni][2] * inv1, o[ni][3] * inv1);
    }
}

// ---------------------------------------------------------------------------
extern "C" void kernel_launch(void* const* d_in, const int* in_sizes, int n_in,
                              void* d_out, int out_size)
{
    const float* Xk = (const float*)d_in[0];
    const float* Xv = (const float*)d_in[1];
    const float* Xq = (const float*)d_in[2];
    const float* Wk = (const float*)d_in[3];
    const float* Wv = (const float*)d_in[4];
    const float* Wq = (const float*)d_in[5];
    const float* Wo = (const float*)d_in[6];
    const float* bo = (const float*)d_in[7];
    float* out = (float*)d_out;

    cudaFuncSetAttribute(proj_tc, cudaFuncAttributeMaxDynamicSharedMemorySize, GEMM_SMEM);
    cudaFuncSetAttribute(outproj_tc, cudaFuncAttributeMaxDynamicSharedMemorySize, GEMM_SMEM);
    cudaFuncSetAttribute(attn_tc, cudaFuncAttributeMaxDynamicSharedMemorySize, ATTN_SMEM);

    // 0) convert inputs to fp16 + transpose weights (Wq pre-scaled by 1/32)
    cvt_inputs<<<dim3(2048, 3), 256>>>(Xk, Xv, Xq);
    transpose_all<<<dim3(32, 32, 4), 256>>>(Wk, Wv, Wq, Wo);
    // 1) QKV projections (fp16 mma, 128x128 CTA, 2 CTAs/SM — R13 best)
    proj_tc<<<dim3(32, 8, 3), 256, GEMM_SMEM>>>();
    // 2) causal flash attention (fp16 mma, 64-q blocks, 3 CTAs/SM — R14 best)
    attn_tc<<<dim3(BH, 16), 128, ATTN_SMEM>>>();
    // 3) output projection + bias + relu (fp16 mma, 2 CTAs/SM)
    outproj_tc<<<dim3(32, 8), 256, GEMM_SMEM>>>(bo, out);
}

// round 16
// speedup vs baseline: 1.0901x; 1.0357x over previous
#include <cuda_runtime.h>
#include <cuda_fp16.h>
#include <cstdint>

// Problem constants
#define BNUM 4
#define SEQ  1024
#define EMBD 1024
#define NH   16
#define HD   64
#define BH   (BNUM * NH)
#define NEG_INF __int_as_float(0xff800000)
#define LOG2E 1.4426950408889634f

// Scratch (allocation-free contract: __device__ globals) — fp16 data plane
__device__ __half g_q[BH * SEQ * HD];          // [bh][s][d], pre-scaled by log2e/32
__device__ __half g_k[BH * SEQ * HD];          // [bh][s][d]
__device__ __half g_vT[BH * HD * SEQ];         // [bh][d][s]
__device__ __half g_ctx[BNUM * SEQ * EMBD];    // concat ctx
__device__ __half g_xh[3 * BNUM * SEQ * EMBD]; // fp16-converted inputs k/v/q
// Transposed (B = [N,K] K-major) weights, fp16 (Wq pre-scaled by log2e/32)
__device__ __half g_wT[3 * EMBD * EMBD];       // k/v/q
__device__ __half g_woT[EMBD * EMBD];

__device__ __forceinline__ uint32_t smem_u32(const void* p) {
    uint32_t a;
    asm("{ .reg .u64 t; cvta.to.shared.u64 t, %1; cvt.u32.u64 %0, t; }"
        : "=r"(a) : "l"(p));
    return a;
}
__device__ __forceinline__ float ex2(float x) {
    float y; asm("ex2.approx.f32 %0, %1;" : "=f"(y) : "f"(x)); return y;
}

__device__ __forceinline__ void mma_f16(float (&d)[4], const uint32_t (&a)[4],
                                        const uint32_t b0, const uint32_t b1) {
    asm volatile(
        "mma.sync.aligned.m16n8k16.row.col.f32.f16.f16.f32 "
        "{%0,%1,%2,%3}, {%4,%5,%6,%7}, {%8,%9}, {%0,%1,%2,%3};"
        : "+f"(d[0]), "+f"(d[1]), "+f"(d[2]), "+f"(d[3])
        : "r"(a[0]), "r"(a[1]), "r"(a[2]), "r"(a[3]), "r"(b0), "r"(b1));
}

#define LDMX4(r, addr) \
    asm volatile("ldmatrix.sync.aligned.m8n8.x4.shared.b16 {%0,%1,%2,%3}, [%4];" \
        : "=r"((r)[0]), "=r"((r)[1]), "=r"((r)[2]), "=r"((r)[3]) : "r"(addr))

#define CP16(dst, src) \
    asm volatile("cp.async.cg.shared.global [%0], [%1], 16;" :: "r"(dst), "l"(src))
#define CP_COMMIT() asm volatile("cp.async.commit_group;" ::: "memory")
template<int N> __device__ __forceinline__ void cp_wait() {
    asm volatile("cp.async.wait_group %0;" :: "n"(N) : "memory");
}

// ---------------------------------------------------------------------------
// fp16 tensor-core GEMM (best measured): C[128x128] = A @ Bt^T,
// K=1024, BK=64, 8 warps (4m x 2n), warp tile 32x64, 3-stage cp.async,
// ldmatrix fragments, 2 CTAs/SM. 8x16B-chunk XOR swizzle (64 fp16 = 128B/row).
// ---------------------------------------------------------------------------
#define TILE_BYTES 16384                // 128 rows * 8 chunks * 16B
#define GEMM_SMEM  (3 * 2 * TILE_BYTES) // 96KB

__device__ __forceinline__ void gemm_f16(const __half* __restrict__ A,
                                         const __half* __restrict__ Bt,
                                         char* sm, float (&c)[2][8][4])
{
    const int tid  = threadIdx.x;
    const int lane = tid & 31;
    const int warp = tid >> 5;
    const int m0   = blockIdx.x * 128;
    const int n0   = blockIdx.y * 128;
    const uint32_t sb = smem_u32(sm);

    auto issue = [&](int stage, int k0) {
        const uint32_t sa  = sb + stage * 2 * TILE_BYTES;
        const uint32_t sbb = sa + TILE_BYTES;
        #pragma unroll
        for (int i = 0; i < 4; i++) {
            const int idx = i * 256 + tid;
            const int row = idx >> 3, ch = idx & 7;
            const uint32_t off = (uint32_t)((row << 3) + (ch ^ (row & 7))) << 4;
            CP16(sa  + off, A  + (size_t)(m0 + row) * EMBD + k0 + ch * 8);
            CP16(sbb + off, Bt + (size_t)(n0 + row) * EMBD + k0 + ch * 8);
        }
        CP_COMMIT();
    };

    issue(0, 0);
    issue(1, 64);

    const int l7   = lane & 7;
    const int wm   = (warp & 3) * 32;                  // 4x2 warp grid
    const int wn   = (warp >> 2) * 64;
    const int aRow = wm + l7 + ((lane >> 3) & 1) * 8;  // + mi*16
    const int aChO = lane >> 4;                        // klo/khi 16B chunk
    const int bRow = wn + l7 + (lane >> 4) * 8;        // + p*16
    const int bChO = (lane >> 3) & 1;

    for (int ch = 0; ch < 16; ch++) {
        const int st = ch % 3;
        if (ch < 14) cp_wait<1>(); else cp_wait<0>();
        __syncthreads();
        if (ch + 2 < 16) issue((ch + 2) % 3, (ch + 2) * 64);

        const uint32_t sa  = sb + st * 2 * TILE_BYTES;
        const uint32_t sbb = sa + TILE_BYTES;

        #pragma unroll
        for (int ks = 0; ks < 4; ks++) {       // 4 k16 steps per BK=64
            uint32_t af[2][4], bq[4][4];
            #pragma unroll
            for (int mi = 0; mi < 2; mi++) {
                const int row = aRow + mi * 16;
                const uint32_t addr =
                    sa + ((uint32_t)((row << 3) + ((ks * 2 + aChO) ^ (row & 7))) << 4);
                LDMX4(af[mi], addr);
            }
            #pragma unroll
            for (int p = 0; p < 4; p++) {
                const int row = bRow + p * 16;
                const uint32_t addr =
                    sbb + ((uint32_t)((row << 3) + ((ks * 2 + bChO) ^ (row & 7))) << 4);
                LDMX4(bq[p], addr);
            }
            #pragma unroll
            for (int mi = 0; mi < 2; mi++)
                #pragma unroll
                for (int ni = 0; ni < 8; ni++)
                    mma_f16(c[mi][ni], af[mi],
                            bq[ni >> 1][(ni & 1) * 2],
                            bq[ni >> 1][(ni & 1) * 2 + 1]);
        }
    }
}

// Projection: A = g_xh[z], writes fp16 Q (pre-scaled via Wq) / K and V^T
__global__ __launch_bounds__(256, 2) void proj_tc()
{
    extern __shared__ char smc[];
    const int z = blockIdx.z;
    const __half* A  = g_xh + (size_t)z * BNUM * SEQ * EMBD;
    const __half* Bt = g_wT + (size_t)z * EMBD * EMBD;

    float c[2][8][4] = {};
    gemm_f16(A, Bt, smc, c);

    const int tid = threadIdx.x;
    const int lane = tid & 31, warp = tid >> 5;
    const int wm = (warp & 3) * 32, wn = (warp >> 2) * 64;
    const int g = lane >> 2, tg = lane & 3;
    const int m0 = blockIdx.x * 128, n0 = blockIdx.y * 128;

    if (z == 1) {
        // V -> g_vT [bh][d][s]
        #pragma unroll
        for (int mi = 0; mi < 2; mi++) {
            #pragma unroll
            for (int ni = 0; ni < 8; ni++) {
                const int n = n0 + wn + ni * 8 + tg * 2;
                const int h = n >> 6, d = n & 63;
                #pragma unroll
                for (int half = 0; half < 2; half++) {
                    const int m = m0 + wm + mi * 16 + g + half * 8;
                    const int b = m >> 10, s = m & 1023;
                    const size_t base = (size_t)(b * NH + h) * HD;
                    g_vT[(base + d)     * SEQ + s] = __float2half_rn(c[mi][ni][half * 2]);
                    g_vT[(base + d + 1) * SEQ + s] = __float2half_rn(c[mi][ni][half * 2 + 1]);
                }
            }
        }
    } else {
        __half* Out = (z == 0) ? g_k : g_q;
        #pragma unroll
        for (int mi = 0; mi < 2; mi++) {
            #pragma unroll
            for (int ni = 0; ni < 8; ni++) {
                const int n = n0 + wn + ni * 8 + tg * 2;
                const int h = n >> 6, d = n & 63;
                #pragma unroll
                for (int half = 0; half < 2; half++) {
                    const int m = m0 + wm + mi * 16 + g + half * 8;
                    const int b = m >> 10, s = m & 1023;
                    *(__half2*)&Out[((size_t)(b * NH + h) * SEQ + s) * HD + d] =
                        __floats2half2_rn(c[mi][ni][half * 2], c[mi][ni][half * 2 + 1]);
                }
            }
        }
    }
}

// Output projection: A = g_ctx (fp16), Bt = g_woT, bias + relu, fp32 out
__global__ __launch_bounds__(256, 2) void outproj_tc(const float* __restrict__ bo,
                                                     float* __restrict__ out)
{
    extern __shared__ char smc[];
    float c[2][8][4] = {};
    gemm_f16(g_ctx, g_woT, smc, c);

    const int tid = threadIdx.x;
    const int lane = tid & 31, warp = tid >> 5;
    const int wm = (warp & 3) * 32, wn = (warp >> 2) * 64;
    const int g = lane >> 2, tg = lane & 3;
    const int m0 = blockIdx.x * 128, n0 = blockIdx.y * 128;

    #pragma unroll
    for (int mi = 0; mi < 2; mi++) {
        #pragma unroll
        for (int ni = 0; ni < 8; ni++) {
            const int n = n0 + wn + ni * 8 + tg * 2;
            const float b0 = bo[n], b1 = bo[n + 1];
            #pragma unroll
            for (int half = 0; half < 2; half++) {
                const int m = m0 + wm + mi * 16 + g + half * 8;
                float2 v = make_float2(fmaxf(c[mi][ni][half * 2]     + b0, 0.0f),
                                       fmaxf(c[mi][ni][half * 2 + 1] + b1, 0.0f));
                *(float2*)&out[(size_t)m * EMBD + n] = v;
            }
        }
    }
}

// ---------------------------------------------------------------------------
// Merged prep (one launch): z 0..2 input fp32->fp16 conversion,
// z 3..5 proj weight transposes (Wq scaled by log2e/32), z 6 Wo transpose.
// ---------------------------------------------------------------------------
__global__ __launch_bounds__(256) void prep_all(const float* __restrict__ Xk,
                                                const float* __restrict__ Xv,
                                                const float* __restrict__ Xq,
                                                const float* __restrict__ Wk,
                                                const float* __restrict__ Wv,
                                                const float* __restrict__ Wq,
                                                const float* __restrict__ Wo)
{
    const int z = blockIdx.z;
    const int tid = threadIdx.x;

    if (z < 3) {
        const float* X = (z == 0) ? Xk : (z == 1) ? Xv : Xq;
        __half* D = g_xh + (size_t)z * BNUM * SEQ * EMBD;
        const size_t i = (size_t)(blockIdx.x * 256 + tid) * 8;
        float4 v1 = *(const float4*)(X + i);
        float4 v2 = *(const float4*)(X + i + 4);
        __half2 h[4] = { __floats2half2_rn(v1.x, v1.y), __floats2half2_rn(v1.z, v1.w),
                         __floats2half2_rn(v2.x, v2.y), __floats2half2_rn(v2.z, v2.w) };
        *(uint4*)(D + i) = *(uint4*)h;
        return;
    }

    if (blockIdx.x >= 1024) return;
    __shared__ float sm[32][33];
    const int bx = blockIdx.x & 31;
    const int by = blockIdx.x >> 5;
    const int k0 = by * 32;

    if (z < 6) {
        const int w = z - 3;
        const float* W = (w == 0) ? Wk : (w == 1) ? Wv : Wq;
        const float scale = (w == 2) ? (LOG2E / 32.0f) : 1.0f;
        __half* WT = g_wT + (size_t)w * EMBD * EMBD;
        const int h  = bx & 15;
        const int d0 = (bx >> 4) * 32;
        // need bx in [0,32): h 0..15, d-half 0..1 -> uses bx fully; by 0..31
        for (int idx = tid; idx < 1024; idx += 256) {
            const int r = idx >> 5, cdx = idx & 31;
            sm[r][cdx] = W[((size_t)h * EMBD + (k0 + r)) * HD + d0 + cdx] * scale;
        }
        __syncthreads();
        for (int idx = tid; idx < 1024; idx += 256) {
            const int dd = idx >> 5, kk = idx & 31;
            WT[(size_t)(h * HD + d0 + dd) * EMBD + k0 + kk] = __float2half_rn(sm[kk][dd]);
        }
    } else {
        const int n0 = bx * 32;
        for (int idx = tid; idx < 1024; idx += 256) {
            const int r = idx >> 5, cdx = idx & 31;
            sm[r][cdx] = Wo[(size_t)(k0 + r) * EMBD + n0 + cdx];
        }
        __syncthreads();
        for (int idx = tid; idx < 1024; idx += 256) {
            const int rr = idx >> 5, cc = idx & 31;
            g_woT[(size_t)(n0 + rr) * EMBD + k0 + cc] = __float2half_rn(sm[cc][rr]);
        }
    }
}

// ---------------------------------------------------------------------------
// fp16 tensor-core flash attention, 128-thread CTAs (64 q rows), 3 CTAs/SM.
// Logits arrive in base-2 domain (Wq pre-scaled by log2e/32) -> softmax uses
// raw ex2.approx, no per-element multiply.
// ---------------------------------------------------------------------------
#define KP 72                                  // P pitch in halves (144B rows)
#define ATT_TILE 8192                          // 64 rows * 8 chunks * 16B
#define ATTN_SMEM (4 * ATT_TILE + 4 * 16 * KP * (int)sizeof(__half))

__device__ __forceinline__ uint32_t att_off(int row, int ch) {
    return (uint32_t)((row << 3) + (ch ^ (row & 7))) << 4;
}

__global__ __launch_bounds__(128, 3) void attn_tc()
{
    extern __shared__ char smc[];
    const uint32_t sb = smem_u32(smc);
    __half* Ps = (__half*)(smc + 4 * ATT_TILE);   // [4 warps][16 q][KP keys]

    const int bh = blockIdx.x;
    const int qt = 15 - blockIdx.y;       // heavy tiles first
    const int q0 = qt * 64;
    const int tid = threadIdx.x, lane = tid & 31, warp = tid >> 5;
    const int g = lane >> 2, tg = lane & 3;
    const int l7 = lane & 7;
    const int fRowO = l7 + (lane >> 4) * 8;      // B-fragment row offset
    const int fChO  = (lane >> 3) & 1;           // B-fragment chunk offset
    const int wq = q0 + warp * 16;

    const __half* Qg = g_q  + (size_t)bh * SEQ * HD;
    const __half* Kg = g_k  + (size_t)bh * SEQ * HD;
    const __half* Vg = g_vT + (size_t)bh * HD * SEQ;
    __half* Pw = Ps + warp * 16 * KP;

    // P A-fragment ldmatrix base (m16n8k16 a-frag lane mapping)
    const uint32_t pBase = smem_u32(Pw) +
        (uint32_t)(l7 + ((lane >> 3) & 1) * 8) * KP * 2 + (uint32_t)(lane >> 4) * 16;

    auto issueKV = [&](int kt) {
        const int k0 = kt * 64;
        const uint32_t kb = sb + (kt & 1) * ATT_TILE;
        const uint32_t vb = sb + 2 * ATT_TILE + (kt & 1) * ATT_TILE;
        #pragma unroll
        for (int i = 0; i < 4; i++) {
            const int idx = i * 128 + tid;
            const int row = idx >> 3, ch = idx & 7;
            const uint32_t o = att_off(row, ch);
            CP16(kb + o, Kg + (size_t)(k0 + row) * HD + ch * 8);
            CP16(vb + o, Vg + (size_t)row * SEQ + k0 + ch * 8);
        }
        CP_COMMIT();
    };

    // Q fragments (pre-scaled in gmem): 4 k16-steps over HD=64
    uint32_t aq[4][4];
    #pragma unroll
    for (int kk = 0; kk < 4; kk++) {
        aq[kk][0] = *(const uint32_t*)(Qg + (size_t)(wq + g)     * HD + kk * 16 + tg * 2);
        aq[kk][1] = *(const uint32_t*)(Qg + (size_t)(wq + g + 8) * HD + kk * 16 + tg * 2);
        aq[kk][2] = *(const uint32_t*)(Qg + (size_t)(wq + g)     * HD + kk * 16 + 8 + tg * 2);
        aq[kk][3] = *(const uint32_t*)(Qg + (size_t)(wq + g + 8) * HD + kk * 16 + 8 + tg * 2);
    }

    float o[8][4] = {};
    float m_r[2] = { NEG_INF, NEG_INF };
    float l_r[2] = { 0.0f, 0.0f };

    const int ktend = qt + 1;
    issueKV(0);

    for (int kt = 0; kt < ktend; kt++) {
        const int k0 = kt * 64;
        cp_wait<0>();
        __syncthreads();
        if (kt + 1 < ktend) issueKV(kt + 1);

        const uint32_t kb = sb + (kt & 1) * ATT_TILE;
        const uint32_t vb = sb + 2 * ATT_TILE + (kt & 1) * ATT_TILE;

        // S = (Q*log2e/32) K^T  (base-2 logits)
        float cs[8][4] = {};
        #pragma unroll
        for (int kk = 0; kk < 4; kk++) {
            const int ch = 2 * kk + fChO;
            #pragma unroll
            for (int n16 = 0; n16 < 4; n16++) {
                uint32_t bk[4];
                LDMX4(bk, kb + att_off(n16 * 16 + fRowO, ch));
                mma_f16(cs[2 * n16],     aq[kk], bk[0], bk[1]);
                mma_f16(cs[2 * n16 + 1], aq[kk], bk[2], bk[3]);
            }
        }

        // causal mask (only the diagonal tile can cross)
        if (kt == qt) {
            #pragma unroll
            for (int ni = 0; ni < 8; ni++) {
                #pragma unroll
                for (int e = 0; e < 4; e++) {
                    const int q = wq + g + ((e >> 1) << 3);
                    const int k = k0 + ni * 8 + tg * 2 + (e & 1);
                    if (k > q) cs[ni][e] = NEG_INF;
                }
            }
        }

        // online softmax in base-2 (rows g and g+8), quad reductions
        #pragma unroll
        for (int hh = 0; hh < 2; hh++) {
            float mx = NEG_INF;
            #pragma unroll
            for (int ni = 0; ni < 8; ni++)
                mx = fmaxf(mx, fmaxf(cs[ni][2 * hh], cs[ni][2 * hh + 1]));
            mx = fmaxf(mx, __shfl_xor_sync(0xffffffff, mx, 1));
            mx = fmaxf(mx, __shfl_xor_sync(0xffffffff, mx, 2));
            const float mnew = fmaxf(m_r[hh], mx);
            const float alpha = ex2(m_r[hh] - mnew);
            float sum = 0.0f;
            #pragma unroll
            for (int ni = 0; ni < 8; ni++) {
                const float p0 = ex2(cs[ni][2 * hh]     - mnew);
                const float p1 = ex2(cs[ni][2 * hh + 1] - mnew);
                cs[ni][2 * hh] = p0; cs[ni][2 * hh + 1] = p1;
                sum += p0 + p1;
            }
            sum += __shfl_xor_sync(0xffffffff, sum, 1);
            sum += __shfl_xor_sync(0xffffffff, sum, 2);
            l_r[hh] = l_r[hh] * alpha + sum;
            m_r[hh] = mnew;
            #pragma unroll
            for (int ni = 0; ni < 8; ni++) {
                o[ni][2 * hh] *= alpha; o[ni][2 * hh + 1] *= alpha;
            }
        }

        // P -> warp-private SMEM (fp16)
        #pragma unroll
        for (int ni = 0; ni < 8; ni++) {
            *(__half2*)&Pw[g * KP + ni * 8 + tg * 2] =
                __floats2half2_rn(cs[ni][0], cs[ni][1]);
            *(__half2*)&Pw[(g + 8) * KP + ni * 8 + tg * 2] =
                __floats2half2_rn(cs[ni][2], cs[ni][3]);
        }
        __syncwarp();

        // O += P V   (P A-frags and V^T B-frags via ldmatrix, 4 k16-steps)
        #pragma unroll
        for (int kk = 0; kk < 4; kk++) {
            uint32_t ap[4];
            LDMX4(ap, pBase + kk * 32);
            const int ch = 2 * kk + fChO;
            #pragma unroll
            for (int n16 = 0; n16 < 4; n16++) {
                uint32_t bv[4];
                LDMX4(bv, vb + att_off(n16 * 16 + fRowO, ch));
                mma_f16(o[2 * n16],     ap, bv[0], bv[1]);
                mma_f16(o[2 * n16 + 1], ap, bv[2], bv[3]);
            }
        }
    }

    // epilogue: normalize and write concat ctx (fp16 for outproj)
    const int b = bh >> 4;
    const int h4 = bh & 15;
    const float inv0 = 1.0f / l_r[0];
    const float inv1 = 1.0f / l_r[1];
    #pragma unroll
    for (int ni = 0; ni < 8; ni++) {
        const int d = h4 * 64 + ni * 8 + tg * 2;
        const int r0 = wq + g, r1 = wq + g + 8;
        *(__half2*)&g_ctx[(size_t)(b * SEQ + r0) * EMBD + d] =
            __floats2half2_rn(o[ni][0] * inv0, o[ni][1] * inv0);
        *(__half2*)&g_ctx[(size_t)(b * SEQ + r1) * EMBD + d] =
            __floats2half2_rn(o[ni][2] * inv1, o[ni][3] * inv1);
    }
}

// ---------------------------------------------------------------------------
extern "C" void kernel_launch(void* const* d_in, const int* in_sizes, int n_in,
                              void* d_out, int out_size)
{
    const float* Xk = (const float*)d_in[0];
    const float* Xv = (const float*)d_in[1];
    const float* Xq = (const float*)d_in[2];
    const float* Wk = (const float*)d_in[3];
    const float* Wv = (const float*)d_in[4];
    const float* Wq = (const float*)d_in[5];
    const float* Wo = (const float*)d_in[6];
    const float* bo = (const float*)d_in[7];
    float* out = (float*)d_out;

    cudaFuncSetAttribute(proj_tc, cudaFuncAttributeMaxDynamicSharedMemorySize, GEMM_SMEM);
    cudaFuncSetAttribute(outproj_tc, cudaFuncAttributeMaxDynamicSharedMemorySize, GEMM_SMEM);
    cudaFuncSetAttribute(attn_tc, cudaFuncAttributeMaxDynamicSharedMemorySize, ATTN_SMEM);

    // 0) one prep launch: cvt inputs + all weight transposes (Wq * log2e/32)
    prep_all<<<dim3(2048, 1, 7), 256>>>(Xk, Xv, Xq, Wk, Wv, Wq, Wo);
    // 1) QKV projections (fp16 mma, 128x128 CTA, 2 CTAs/SM)
    proj_tc<<<dim3(32, 8, 3), 256, GEMM_SMEM>>>();
    // 2) causal flash attention (fp16 mma, base-2 softmax, 3 CTAs/SM)
    attn_tc<<<dim3(BH, 16), 128, ATTN_SMEM>>>();
    // 3) output projection + bias + relu (fp16 mma, 2 CTAs/SM)
    outproj_tc<<<dim3(32, 8), 256, GEMM_SMEM>>>(bo, out);
}

// round 17
// speedup vs baseline: 1.1020x; 1.0109x over previous
#include <cuda_runtime.h>
#include <cuda_fp16.h>
#include <cstdint>

// Problem constants
#define BNUM 4
#define SEQ  1024
#define EMBD 1024
#define NH   16
#define HD   64
#define BH   (BNUM * NH)
#define NEG_INF __int_as_float(0xff800000)
#define LOG2E 1.4426950408889634f

// Scratch (allocation-free contract: __device__ globals) — fp16 data plane
__device__ __half g_q[BH * SEQ * HD];          // [bh][s][d], pre-scaled by log2e/32
__device__ __half g_k[BH * SEQ * HD];          // [bh][s][d]
__device__ __half g_vT[BH * HD * SEQ];         // [bh][d][s]
__device__ __half g_ctx[BNUM * SEQ * EMBD];    // concat ctx
__device__ __half g_xh[3 * BNUM * SEQ * EMBD]; // fp16-converted inputs k/v/q
// Transposed (B = [N,K] K-major) weights, fp16 (Wq pre-scaled by log2e/32)
__device__ __half g_wT[3 * EMBD * EMBD];       // k/v/q
__device__ __half g_woT[EMBD * EMBD];

__device__ __forceinline__ uint32_t smem_u32(const void* p) {
    uint32_t a;
    asm("{ .reg .u64 t; cvta.to.shared.u64 t, %1; cvt.u32.u64 %0, t; }"
        : "=r"(a) : "l"(p));
    return a;
}
__device__ __forceinline__ float ex2(float x) {
    float y; asm("ex2.approx.f32 %0, %1;" : "=f"(y) : "f"(x)); return y;
}
__device__ __forceinline__ uint32_t pack_h2(float lo, float hi) {
    __half2 h = __floats2half2_rn(lo, hi);
    return *(uint32_t*)&h;
}

__device__ __forceinline__ void mma_f16(float (&d)[4], const uint32_t (&a)[4],
                                        const uint32_t b0, const uint32_t b1) {
    asm volatile(
        "mma.sync.aligned.m16n8k16.row.col.f32.f16.f16.f32 "
        "{%0,%1,%2,%3}, {%4,%5,%6,%7}, {%8,%9}, {%0,%1,%2,%3};"
        : "+f"(d[0]), "+f"(d[1]), "+f"(d[2]), "+f"(d[3])
        : "r"(a[0]), "r"(a[1]), "r"(a[2]), "r"(a[3]), "r"(b0), "r"(b1));
}

#define LDMX4(r, addr) \
    asm volatile("ldmatrix.sync.aligned.m8n8.x4.shared.b16 {%0,%1,%2,%3}, [%4];" \
        : "=r"((r)[0]), "=r"((r)[1]), "=r"((r)[2]), "=r"((r)[3]) : "r"(addr))

#define CP16(dst, src) \
    asm volatile("cp.async.cg.shared.global [%0], [%1], 16;" :: "r"(dst), "l"(src))
#define CP_COMMIT() asm volatile("cp.async.commit_group;" ::: "memory")
template<int N> __device__ __forceinline__ void cp_wait() {
    asm volatile("cp.async.wait_group %0;" :: "n"(N) : "memory");
}

// ---------------------------------------------------------------------------
// fp16 tensor-core GEMM (best measured): C[128x128] = A @ Bt^T,
// K=1024, BK=64, 8 warps (4m x 2n), warp tile 32x64, 3-stage cp.async,
// ldmatrix fragments, 2 CTAs/SM. 8x16B-chunk XOR swizzle (64 fp16 = 128B/row).
// ---------------------------------------------------------------------------
#define TILE_BYTES 16384                // 128 rows * 8 chunks * 16B
#define GEMM_SMEM  (3 * 2 * TILE_BYTES) // 96KB

__device__ __forceinline__ void gemm_f16(const __half* __restrict__ A,
                                         const __half* __restrict__ Bt,
                                         char* sm, float (&c)[2][8][4])
{
    const int tid  = threadIdx.x;
    const int lane = tid & 31;
    const int warp = tid >> 5;
    const int m0   = blockIdx.x * 128;
    const int n0   = blockIdx.y * 128;
    const uint32_t sb = smem_u32(sm);

    auto issue = [&](int stage, int k0) {
        const uint32_t sa  = sb + stage * 2 * TILE_BYTES;
        const uint32_t sbb = sa + TILE_BYTES;
        #pragma unroll
        for (int i = 0; i < 4; i++) {
            const int idx = i * 256 + tid;
            const int row = idx >> 3, ch = idx & 7;
            const uint32_t off = (uint32_t)((row << 3) + (ch ^ (row & 7))) << 4;
            CP16(sa  + off, A  + (size_t)(m0 + row) * EMBD + k0 + ch * 8);
            CP16(sbb + off, Bt + (size_t)(n0 + row) * EMBD + k0 + ch * 8);
        }
        CP_COMMIT();
    };

    issue(0, 0);
    issue(1, 64);

    const int l7   = lane & 7;
    const int wm   = (warp & 3) * 32;                  // 4x2 warp grid
    const int wn   = (warp >> 2) * 64;
    const int aRow = wm + l7 + ((lane >> 3) & 1) * 8;  // + mi*16
    const int aChO = lane >> 4;                        // klo/khi 16B chunk
    const int bRow = wn + l7 + (lane >> 4) * 8;        // + p*16
    const int bChO = (lane >> 3) & 1;

    for (int ch = 0; ch < 16; ch++) {
        const int st = ch % 3;
        if (ch < 14) cp_wait<1>(); else cp_wait<0>();
        __syncthreads();
        if (ch + 2 < 16) issue((ch + 2) % 3, (ch + 2) * 64);

        const uint32_t sa  = sb + st * 2 * TILE_BYTES;
        const uint32_t sbb = sa + TILE_BYTES;

        #pragma unroll
        for (int ks = 0; ks < 4; ks++) {       // 4 k16 steps per BK=64
            uint32_t af[2][4], bq[4][4];
            #pragma unroll
            for (int mi = 0; mi < 2; mi++) {
                const int row = aRow + mi * 16;
                const uint32_t addr =
                    sa + ((uint32_t)((row << 3) + ((ks * 2 + aChO) ^ (row & 7))) << 4);
                LDMX4(af[mi], addr);
            }
            #pragma unroll
            for (int p = 0; p < 4; p++) {
                const int row = bRow + p * 16;
                const uint32_t addr =
                    sbb + ((uint32_t)((row << 3) + ((ks * 2 + bChO) ^ (row & 7))) << 4);
                LDMX4(bq[p], addr);
            }
            #pragma unroll
            for (int mi = 0; mi < 2; mi++)
                #pragma unroll
                for (int ni = 0; ni < 8; ni++)
                    mma_f16(c[mi][ni], af[mi],
                            bq[ni >> 1][(ni & 1) * 2],
                            bq[ni >> 1][(ni & 1) * 2 + 1]);
        }
    }
}

// Projection: A = g_xh[z], writes fp16 Q (pre-scaled via Wq) / K and V^T
__global__ __launch_bounds__(256, 2) void proj_tc()
{
    extern __shared__ char smc[];
    const int z = blockIdx.z;
    const __half* A  = g_xh + (size_t)z * BNUM * SEQ * EMBD;
    const __half* Bt = g_wT + (size_t)z * EMBD * EMBD;

    float c[2][8][4] = {};
    gemm_f16(A, Bt, smc, c);

    const int tid = threadIdx.x;
    const int lane = tid & 31, warp = tid >> 5;
    const int wm = (warp & 3) * 32, wn = (warp >> 2) * 64;
    const int g = lane >> 2, tg = lane & 3;
    const int m0 = blockIdx.x * 128, n0 = blockIdx.y * 128;

    if (z == 1) {
        // V -> g_vT [bh][d][s]
        #pragma unroll
        for (int mi = 0; mi < 2; mi++) {
            #pragma unroll
            for (int ni = 0; ni < 8; ni++) {
                const int n = n0 + wn + ni * 8 + tg * 2;
                const int h = n >> 6, d = n & 63;
                #pragma unroll
                for (int half = 0; half < 2; half++) {
                    const int m = m0 + wm + mi * 16 + g + half * 8;
                    const int b = m >> 10, s = m & 1023;
                    const size_t base = (size_t)(b * NH + h) * HD;
                    g_vT[(base + d)     * SEQ + s] = __float2half_rn(c[mi][ni][half * 2]);
                    g_vT[(base + d + 1) * SEQ + s] = __float2half_rn(c[mi][ni][half * 2 + 1]);
                }
            }
        }
    } else {
        __half* Out = (z == 0) ? g_k : g_q;
        #pragma unroll
        for (int mi = 0; mi < 2; mi++) {
            #pragma unroll
            for (int ni = 0; ni < 8; ni++) {
                const int n = n0 + wn + ni * 8 + tg * 2;
                const int h = n >> 6, d = n & 63;
                #pragma unroll
                for (int half = 0; half < 2; half++) {
                    const int m = m0 + wm + mi * 16 + g + half * 8;
                    const int b = m >> 10, s = m & 1023;
                    *(__half2*)&Out[((size_t)(b * NH + h) * SEQ + s) * HD + d] =
                        __floats2half2_rn(c[mi][ni][half * 2], c[mi][ni][half * 2 + 1]);
                }
            }
        }
    }
}

// Output projection: A = g_ctx (fp16), Bt = g_woT, bias + relu, fp32 out
__global__ __launch_bounds__(256, 2) void outproj_tc(const float* __restrict__ bo,
                                                     float* __restrict__ out)
{
    extern __shared__ char smc[];
    float c[2][8][4] = {};
    gemm_f16(g_ctx, g_woT, smc, c);

    const int tid = threadIdx.x;
    const int lane = tid & 31, warp = tid >> 5;
    const int wm = (warp & 3) * 32, wn = (warp >> 2) * 64;
    const int g = lane >> 2, tg = lane & 3;
    const int m0 = blockIdx.x * 128, n0 = blockIdx.y * 128;

    #pragma unroll
    for (int mi = 0; mi < 2; mi++) {
        #pragma unroll
        for (int ni = 0; ni < 8; ni++) {
            const int n = n0 + wn + ni * 8 + tg * 2;
            const float b0 = bo[n], b1 = bo[n + 1];
            #pragma unroll
            for (int half = 0; half < 2; half++) {
                const int m = m0 + wm + mi * 16 + g + half * 8;
                float2 v = make_float2(fmaxf(c[mi][ni][half * 2]     + b0, 0.0f),
                                       fmaxf(c[mi][ni][half * 2 + 1] + b1, 0.0f));
                *(float2*)&out[(size_t)m * EMBD + n] = v;
            }
        }
    }
}

// ---------------------------------------------------------------------------
// Merged prep (one launch): z 0..2 input fp32->fp16 conversion,
// z 3..5 proj weight transposes (Wq scaled by log2e/32), z 6 Wo transpose.
// ---------------------------------------------------------------------------
__global__ __launch_bounds__(256) void prep_all(const float* __restrict__ Xk,
                                                const float* __restrict__ Xv,
                                                const float* __restrict__ Xq,
                                                const float* __restrict__ Wk,
                                                const float* __restrict__ Wv,
                                                const float* __restrict__ Wq,
                                                const float* __restrict__ Wo)
{
    const int z = blockIdx.z;
    const int tid = threadIdx.x;

    if (z < 3) {
        const float* X = (z == 0) ? Xk : (z == 1) ? Xv : Xq;
        __half* D = g_xh + (size_t)z * BNUM * SEQ * EMBD;
        const size_t i = (size_t)(blockIdx.x * 256 + tid) * 8;
        float4 v1 = *(const float4*)(X + i);
        float4 v2 = *(const float4*)(X + i + 4);
        __half2 h[4] = { __floats2half2_rn(v1.x, v1.y), __floats2half2_rn(v1.z, v1.w),
                         __floats2half2_rn(v2.x, v2.y), __floats2half2_rn(v2.z, v2.w) };
        *(uint4*)(D + i) = *(uint4*)h;
        return;
    }

    if (blockIdx.x >= 1024) return;
    __shared__ float sm[32][33];
    const int bx = blockIdx.x & 31;
    const int by = blockIdx.x >> 5;
    const int k0 = by * 32;

    if (z < 6) {
        const int w = z - 3;
        const float* W = (w == 0) ? Wk : (w == 1) ? Wv : Wq;
        const float scale = (w == 2) ? (LOG2E / 32.0f) : 1.0f;
        __half* WT = g_wT + (size_t)w * EMBD * EMBD;
        const int h  = bx & 15;
        const int d0 = (bx >> 4) * 32;
        for (int idx = tid; idx < 1024; idx += 256) {
            const int r = idx >> 5, cdx = idx & 31;
            sm[r][cdx] = W[((size_t)h * EMBD + (k0 + r)) * HD + d0 + cdx] * scale;
        }
        __syncthreads();
        for (int idx = tid; idx < 1024; idx += 256) {
            const int dd = idx >> 5, kk = idx & 31;
            WT[(size_t)(h * HD + d0 + dd) * EMBD + k0 + kk] = __float2half_rn(sm[kk][dd]);
        }
    } else {
        const int n0 = bx * 32;
        for (int idx = tid; idx < 1024; idx += 256) {
            const int r = idx >> 5, cdx = idx & 31;
            sm[r][cdx] = Wo[(size_t)(k0 + r) * EMBD + n0 + cdx];
        }
        __syncthreads();
        for (int idx = tid; idx < 1024; idx += 256) {
            const int rr = idx >> 5, cc = idx & 31;
            g_woT[(size_t)(n0 + rr) * EMBD + k0 + cc] = __float2half_rn(sm[cc][rr]);
        }
    }
}

// ---------------------------------------------------------------------------
// fp16 tensor-core flash attention, 128-thread CTAs (64 q rows), 3 CTAs/SM.
// Base-2 softmax (Wq pre-scaled by log2e/32, raw ex2.approx).
// P REGISTER PATH: the m16n8k16 S-accumulator layout coincides with the PV
// A-fragment layout, so P never touches smem — pack cs -> half2 in regs.
// ---------------------------------------------------------------------------
#define ATT_TILE 8192                          // 64 rows * 8 chunks * 16B
#define ATTN_SMEM (4 * ATT_TILE)

__device__ __forceinline__ uint32_t att_off(int row, int ch) {
    return (uint32_t)((row << 3) + (ch ^ (row & 7))) << 4;
}

__global__ __launch_bounds__(128, 3) void attn_tc()
{
    extern __shared__ char smc[];
    const uint32_t sb = smem_u32(smc);

    const int bh = blockIdx.x;
    const int qt = 15 - blockIdx.y;       // heavy tiles first
    const int q0 = qt * 64;
    const int tid = threadIdx.x, lane = tid & 31, warp = tid >> 5;
    const int g = lane >> 2, tg = lane & 3;
    const int l7 = lane & 7;
    const int fRowO = l7 + (lane >> 4) * 8;      // B-fragment row offset
    const int fChO  = (lane >> 3) & 1;           // B-fragment chunk offset
    const int wq = q0 + warp * 16;

    const __half* Qg = g_q  + (size_t)bh * SEQ * HD;
    const __half* Kg = g_k  + (size_t)bh * SEQ * HD;
    const __half* Vg = g_vT + (size_t)bh * HD * SEQ;

    auto issueKV = [&](int kt) {
        const int k0 = kt * 64;
        const uint32_t kb = sb + (kt & 1) * ATT_TILE;
        const uint32_t vb = sb + 2 * ATT_TILE + (kt & 1) * ATT_TILE;
        #pragma unroll
        for (int i = 0; i < 4; i++) {
            const int idx = i * 128 + tid;
            const int row = idx >> 3, ch = idx & 7;
            const uint32_t o = att_off(row, ch);
            CP16(kb + o, Kg + (size_t)(k0 + row) * HD + ch * 8);
            CP16(vb + o, Vg + (size_t)row * SEQ + k0 + ch * 8);
        }
        CP_COMMIT();
    };

    // Q fragments (pre-scaled in gmem): 4 k16-steps over HD=64
    uint32_t aq[4][4];
    #pragma unroll
    for (int kk = 0; kk < 4; kk++) {
        aq[kk][0] = *(const uint32_t*)(Qg + (size_t)(wq + g)     * HD + kk * 16 + tg * 2);
        aq[kk][1] = *(const uint32_t*)(Qg + (size_t)(wq + g + 8) * HD + kk * 16 + tg * 2);
        aq[kk][2] = *(const uint32_t*)(Qg + (size_t)(wq + g)     * HD + kk * 16 + 8 + tg * 2);
        aq[kk][3] = *(const uint32_t*)(Qg + (size_t)(wq + g + 8) * HD + kk * 16 + 8 + tg * 2);
    }

    float o[8][4] = {};
    float m_r[2] = { NEG_INF, NEG_INF };
    float l_r[2] = { 0.0f, 0.0f };

    const int ktend = qt + 1;
    issueKV(0);

    for (int kt = 0; kt < ktend; kt++) {
        const int k0 = kt * 64;
        cp_wait<0>();
        __syncthreads();
        if (kt + 1 < ktend) issueKV(kt + 1);

        const uint32_t kb = sb + (kt & 1) * ATT_TILE;
        const uint32_t vb = sb + 2 * ATT_TILE + (kt & 1) * ATT_TILE;

        // S = (Q*log2e/32) K^T  (base-2 logits)
        float cs[8][4] = {};
        #pragma unroll
        for (int kk = 0; kk < 4; kk++) {
            const int ch = 2 * kk + fChO;
            #pragma unroll
            for (int n16 = 0; n16 < 4; n16++) {
                uint32_t bk[4];
                LDMX4(bk, kb + att_off(n16 * 16 + fRowO, ch));
                mma_f16(cs[2 * n16],     aq[kk], bk[0], bk[1]);
                mma_f16(cs[2 * n16 + 1], aq[kk], bk[2], bk[3]);
            }
        }

        // causal mask (only the diagonal tile can cross)
        if (kt == qt) {
            #pragma unroll
            for (int ni = 0; ni < 8; ni++) {
                #pragma unroll
                for (int e = 0; e < 4; e++) {
                    const int q = wq + g + ((e >> 1) << 3);
                    const int k = k0 + ni * 8 + tg * 2 + (e & 1);
                    if (k > q) cs[ni][e] = NEG_INF;
                }
            }
        }

        // online softmax in base-2 (rows g and g+8), quad reductions
        #pragma unroll
        for (int hh = 0; hh < 2; hh++) {
            float mx = NEG_INF;
            #pragma unroll
            for (int ni = 0; ni < 8; ni++)
                mx = fmaxf(mx, fmaxf(cs[ni][2 * hh], cs[ni][2 * hh + 1]));
            mx = fmaxf(mx, __shfl_xor_sync(0xffffffff, mx, 1));
            mx = fmaxf(mx, __shfl_xor_sync(0xffffffff, mx, 2));
            const float mnew = fmaxf(m_r[hh], mx);
            const float alpha = ex2(m_r[hh] - mnew);
            float sum = 0.0f;
            #pragma unroll
            for (int ni = 0; ni < 8; ni++) {
                const float p0 = ex2(cs[ni][2 * hh]     - mnew);
                const float p1 = ex2(cs[ni][2 * hh + 1] - mnew);
                cs[ni][2 * hh] = p0; cs[ni][2 * hh + 1] = p1;
                sum += p0 + p1;
            }
            sum += __shfl_xor_sync(0xffffffff, sum, 1);
            sum += __shfl_xor_sync(0xffffffff, sum, 2);
            l_r[hh] = l_r[hh] * alpha + sum;
            m_r[hh] = mnew;
            #pragma unroll
            for (int ni = 0; ni < 8; ni++) {
                o[ni][2 * hh] *= alpha; o[ni][2 * hh + 1] *= alpha;
            }
        }

        // pack P accumulators -> fp16 A-fragments (register-only)
        uint32_t pk[8][2];
        #pragma unroll
        for (int ni = 0; ni < 8; ni++) {
            pk[ni][0] = pack_h2(cs[ni][0], cs[ni][1]);   // row g
            pk[ni][1] = pack_h2(cs[ni][2], cs[ni][3]);   // row g+8
        }

        // O += P V   (P A-frags straight from registers; V^T via ldmatrix)
        #pragma unroll
        for (int kk = 0; kk < 4; kk++) {
            const uint32_t ap[4] = { pk[2 * kk][0], pk[2 * kk][1],
                                     pk[2 * kk + 1][0], pk[2 * kk + 1][1] };
            const int ch = 2 * kk + fChO;
            #pragma unroll
            for (int n16 = 0; n16 < 4; n16++) {
                uint32_t bv[4];
                LDMX4(bv, vb + att_off(n16 * 16 + fRowO, ch));
                mma_f16(o[2 * n16],     ap, bv[0], bv[1]);
                mma_f16(o[2 * n16 + 1], ap, bv[2], bv[3]);
            }
        }
    }

    // epilogue: normalize and write concat ctx (fp16 for outproj)
    const int b = bh >> 4;
    const int h4 = bh & 15;
    const float inv0 = 1.0f / l_r[0];
    const float inv1 = 1.0f / l_r[1];
    #pragma unroll
    for (int ni = 0; ni < 8; ni++) {
        const int d = h4 * 64 + ni * 8 + tg * 2;
        const int r0 = wq + g, r1 = wq + g + 8;
        *(__half2*)&g_ctx[(size_t)(b * SEQ + r0) * EMBD + d] =
            __floats2half2_rn(o[ni][0] * inv0, o[ni][1] * inv0);
        *(__half2*)&g_ctx[(size_t)(b * SEQ + r1) * EMBD + d] =
            __floats2half2_rn(o[ni][2] * inv1, o[ni][3] * inv1);
    }
}

// ---------------------------------------------------------------------------
extern "C" void kernel_launch(void* const* d_in, const int* in_sizes, int n_in,
                              void* d_out, int out_size)
{
    const float* Xk = (const float*)d_in[0];
    const float* Xv = (const float*)d_in[1];
    const float* Xq = (const float*)d_in[2];
    const float* Wk = (const float*)d_in[3];
    const float* Wv = (const float*)d_in[4];
    const float* Wq = (const float*)d_in[5];
    const float* Wo = (const float*)d_in[6];
    const float* bo = (const float*)d_in[7];
    float* out = (float*)d_out;

    cudaFuncSetAttribute(proj_tc, cudaFuncAttributeMaxDynamicSharedMemorySize, GEMM_SMEM);
    cudaFuncSetAttribute(outproj_tc, cudaFuncAttributeMaxDynamicSharedMemorySize, GEMM_SMEM);
    cudaFuncSetAttribute(attn_tc, cudaFuncAttributeMaxDynamicSharedMemorySize, ATTN_SMEM);

    // 0) one prep launch: cvt inputs + all weight transposes (Wq * log2e/32)
    prep_all<<<dim3(2048, 1, 7), 256>>>(Xk, Xv, Xq, Wk, Wv, Wq, Wo);
    // 1) QKV projections (fp16 mma, 128x128 CTA, 2 CTAs/SM)
    proj_tc<<<dim3(32, 8, 3), 256, GEMM_SMEM>>>();
    // 2) causal flash attention (fp16 mma, register-P, 3 CTAs/SM)
    attn_tc<<<dim3(BH, 16), 128, ATTN_SMEM>>>();
    // 3) output projection + bias + relu (fp16 mma, 2 CTAs/SM)
    outproj_tc<<<dim3(32, 8), 256, GEMM_SMEM>>>(bo, out);
}